// round 2
// baseline (speedup 1.0000x reference)
#include <cuda_runtime.h>

// Problem constants (fixed shapes from reference)
#define BATCH 32
#define IN_H  128
#define IN_W  512
#define CHAN  32
#define OUT_H 64
#define OUT_W 256

// 8 threads per output point, each handling 4 channels (float4).
// Total threads = B * OUT_H * OUT_W * 8 = 4,194,304.

__global__ void __launch_bounds__(256)
stn_bilinear_kernel(const float* __restrict__ image,
                    const float* __restrict__ theta,
                    float* __restrict__ out)
{
    int t = blockIdx.x * blockDim.x + threadIdx.x;
    const int total = BATCH * OUT_H * OUT_W * (CHAN / 4);
    if (t >= total) return;

    int cg  = t & 7;          // channel group 0..7 (4 floats each)
    int n   = t >> 3;         // output point index
    int wx  = n % OUT_W;
    int r   = n / OUT_W;
    int hy  = r % OUT_H;
    int b   = r / OUT_H;

    // sampling grid in [-1, 1] (linspace, endpoint inclusive)
    float xg = -1.0f + 2.0f * (float)wx / (float)(OUT_W - 1);
    float yg = -1.0f + 2.0f * (float)hy / (float)(OUT_H - 1);

    // theta[b] as 2x3; reference's debug hack: zero row 1 of batch 0, row 0 of batch 1
    const float* th = theta + b * 6;
    float t00 = __ldg(th + 0), t01 = __ldg(th + 1), t02 = __ldg(th + 2);
    float t10 = __ldg(th + 3), t11 = __ldg(th + 4), t12 = __ldg(th + 5);
    if (b == 0) { t10 = 0.0f; t11 = 0.0f; t12 = 0.0f; }
    if (b == 1) { t00 = 0.0f; t01 = 0.0f; t02 = 0.0f; }

    float cx = t00 * xg + t01 * yg + t02;
    float cy = t10 * xg + t11 * yg + t12;

    float x = 0.5f * (cx + 1.0f) * (float)IN_W;   // uses W, not W-1 (matches source)
    float y = 0.5f * (cy + 1.0f) * (float)IN_H;

    // truncation toward zero (matches jnp astype(int32) / C cast)
    int x0 = (int)x;
    int y0 = (int)y;
    int x1 = x0 + 1;
    int y1 = y0 + 1;
    // clip BEFORE computing float weights (matches reference ordering)
    x0 = min(max(x0, 0), IN_W - 1);
    x1 = min(max(x1, 0), IN_W - 1);
    y0 = min(max(y0, 0), IN_H - 1);
    y1 = min(max(y1, 0), IN_H - 1);

    float x0f = (float)x0, x1f = (float)x1;
    float y0f = (float)y0, y1f = (float)y1;

    float wA = (x1f - x) * (y1f - y);
    float wB = (x1f - x) * (y - y0f);
    float wC = (x - x0f) * (y1f - y);
    float wD = (x - x0f) * (y - y0f);

    // image pixel base (in pixels); each pixel = 32 floats = 8 float4
    const float4* __restrict__ img4 = (const float4*)image;
    long long base = (long long)b * (IN_H * IN_W);

    long long iA = (base + (long long)y0 * IN_W + x0) * 8 + cg;
    long long iB = (base + (long long)y1 * IN_W + x0) * 8 + cg;
    long long iC = (base + (long long)y0 * IN_W + x1) * 8 + cg;
    long long iD = (base + (long long)y1 * IN_W + x1) * 8 + cg;

    float4 pA = __ldg(img4 + iA);
    float4 pB = __ldg(img4 + iB);
    float4 pC = __ldg(img4 + iC);
    float4 pD = __ldg(img4 + iD);

    float4 res;
    res.x = pA.x * wA + pB.x * wB + pC.x * wC + pD.x * wD;
    res.y = pA.y * wA + pB.y * wB + pC.y * wC + pD.y * wD;
    res.z = pA.z * wA + pB.z * wB + pC.z * wC + pD.z * wD;
    res.w = pA.w * wA + pB.w * wB + pC.w * wC + pD.w * wD;

    float4* __restrict__ out4 = (float4*)out;
    out4[(long long)n * 8 + cg] = res;
}

extern "C" void kernel_launch(void* const* d_in, const int* in_sizes, int n_in,
                              void* d_out, int out_size)
{
    const float* image = (const float*)d_in[0];
    const float* theta = (const float*)d_in[1];
    float*       out   = (float*)d_out;

    const int total = BATCH * OUT_H * OUT_W * (CHAN / 4);
    const int threads = 256;
    const int blocks = (total + threads - 1) / threads;
    stn_bilinear_kernel<<<blocks, threads>>>(image, theta, out);
}